// round 4
// baseline (speedup 1.0000x reference)
#include <cuda_runtime.h>
#include <math.h>

#define NB 16
#define NW 64
#define NIMG 1024
#define NPIX 4096
#define NYH 33
#define NMODE 2112
#define TSTEPS 20
typedef unsigned long long ull;

// ---------------- device global scratch (no allocations allowed) ----------------
__device__ float  g_h [NIMG*NPIX];              // hidden state [b][w][x][y]
__device__ float  g_z [NIMG*NPIX];              // sigmoid(z)
__device__ float2 g_hf[(size_t)NIMG*NMODE];     // spectrum [img][mode]
__device__ float2 g_zf[(size_t)NIMG*NMODE];
__device__ float2 g_rf[(size_t)NIMG*NMODE];     // r-spec, then n-spec
__device__ float2 g_Wt[3][(size_t)NMODE*4096];  // weights [gate][mode][i*64+o]
__device__ float2 g_tw[64];                     // W64^k forward twiddles

// ---------------- small helpers ----------------
__device__ __forceinline__ ull pack2(float x, float y){
  ull r; asm("mov.b64 %0,{%1,%2};":"=l"(r):"f"(x),"f"(y)); return r;
}
__device__ __forceinline__ ull ffma2(ull a, ull b, ull c){
  ull d; asm("fma.rn.f32x2 %0,%1,%2,%3;":"=l"(d):"l"(a),"l"(b),"l"(c)); return d;
}
__device__ __forceinline__ float2 cadd2(float2 a,float2 b){return make_float2(a.x+b.x,a.y+b.y);}
__device__ __forceinline__ float2 csub2(float2 a,float2 b){return make_float2(a.x-b.x,a.y-b.y);}
__device__ __forceinline__ int brev3i(int i){ return ((i&1)<<2)|(i&2)|((i>>2)&1); }

// ---------------- setup kernels ----------------
__global__ void k_twid(){
  int k = threadIdx.x;
  double s,c; sincospi(-(double)k/32.0,&s,&c);
  g_tw[k] = make_float2((float)c,(float)s);
}

// [io=4096][mode=2112] (re,im planes) -> g_Wt[gate][mode][io] float2
__global__ void k_wtrans(const float* __restrict__ wr, const float* __restrict__ wi, int gate){
  __shared__ float tr[32][33];
  __shared__ float ti[32][33];
  int m0 = blockIdx.x*32, io0 = blockIdx.y*32;
  int tx = threadIdx.x, ty = threadIdx.y;
  for (int r = ty; r < 32; r += 8){
    tr[r][tx] = wr[(size_t)(io0+r)*NMODE + m0 + tx];
    ti[r][tx] = wi[(size_t)(io0+r)*NMODE + m0 + tx];
  }
  __syncthreads();
  float2* dst = g_Wt[gate];
  for (int r = ty; r < 32; r += 8)
    dst[(size_t)(m0+r)*4096 + io0 + tx] = make_float2(tr[tx][r], ti[tx][r]);
}

// h0[b][w][x][y] = x[b][x][y][0]*Wi[w] + bi[w]
__global__ void k_inmap(const float* __restrict__ xin, const float* __restrict__ Wi,
                        const float* __restrict__ bi){
  int idx = blockIdx.x*256 + threadIdx.x;
  int img = idx >> 12, xy = idx & 4095;
  int b = img >> 6, w = img & 63;
  g_h[idx] = xin[(b<<12) + xy]*Wi[w] + bi[w];
}

// ---------------- 64-pt radix-8 FFT core ----------------
template<int SIGN>  // -1 forward, +1 inverse
__device__ __forceinline__ void fft8(float2 v[8]){
  const float C0 = 0.70710678118654752f;
  const float S = (float)SIGN;
  float2 t;
  t=v[1]; v[1]=csub2(v[0],t); v[0]=cadd2(v[0],t);
  t=v[3]; v[3]=csub2(v[2],t); v[2]=cadd2(v[2],t);
  t=v[5]; v[5]=csub2(v[4],t); v[4]=cadd2(v[4],t);
  t=v[7]; v[7]=csub2(v[6],t); v[6]=cadd2(v[6],t);
  t=v[2]; v[2]=csub2(v[0],t); v[0]=cadd2(v[0],t);
  t=make_float2(-S*v[3].y, S*v[3].x); v[3]=csub2(v[1],t); v[1]=cadd2(v[1],t);
  t=v[6]; v[6]=csub2(v[4],t); v[4]=cadd2(v[4],t);
  t=make_float2(-S*v[7].y, S*v[7].x); v[7]=csub2(v[5],t); v[5]=cadd2(v[5],t);
  t=v[4]; v[4]=csub2(v[0],t); v[0]=cadd2(v[0],t);
  t=make_float2(C0*(v[5].x - S*v[5].y), C0*(S*v[5].x + v[5].y));
  v[5]=csub2(v[1],t); v[1]=cadd2(v[1],t);
  t=make_float2(-S*v[6].y, S*v[6].x); v[6]=csub2(v[2],t); v[2]=cadd2(v[2],t);
  t=make_float2(-C0*(v[7].x + S*v[7].y), C0*(S*v[7].x - v[7].y));
  v[7]=csub2(v[3],t); v[3]=cadd2(v[3],t);
}

// one 1-D 64-pt FFT over 64 lines in a 64x65 float2 tile. blockDim.x==256.
// xdim=0: transform along contiguous index; xdim=1: along the strided index.
template<int SIGN>
__device__ void fft64_pass(float2* buf, const float2* stw, int tid, int xdim){
  int rs = xdim ? 65 : 1;      // stride of transform index
  int cs = xdim ? 1 : 65;      // stride of line index
  // step A: DFT8 over n1 (stride-8 sets), twiddle, store at 8*k1+j. thread-local sets.
  #pragma unroll
  for (int q = 0; q < 2; q++){
    int slot = q*256 + tid;
    int line = slot & 63, j = slot >> 6;
    float2 v[8];
    #pragma unroll
    for (int i = 0; i < 8; i++) v[i] = buf[line*cs + (8*brev3i(i)+j)*rs];
    fft8<SIGN>(v);
    #pragma unroll
    for (int k1 = 1; k1 < 8; k1++){
      float2 w = stw[(k1*j) & 63];
      float wy = (SIGN < 0) ? w.y : -w.y;
      float2 a = v[k1];
      v[k1] = make_float2(a.x*w.x - a.y*wy, a.x*wy + a.y*w.x);
    }
    #pragma unroll
    for (int k1 = 0; k1 < 8; k1++) buf[line*cs + (k1*8+j)*rs] = v[k1];
  }
  __syncthreads();
  // step B: DFT8 over n2 (contiguous sets), scatter to natural order.
  float2 vv[2][8];
  #pragma unroll
  for (int q = 0; q < 2; q++){
    int slot = q*256 + tid;
    int line = slot & 63, k1 = slot >> 6;
    #pragma unroll
    for (int i = 0; i < 8; i++) vv[q][i] = buf[line*cs + (k1*8 + brev3i(i))*rs];
    fft8<SIGN>(vv[q]);
  }
  __syncthreads();
  #pragma unroll
  for (int q = 0; q < 2; q++){
    int slot = q*256 + tid;
    int line = slot & 63, k1 = slot >> 6;
    #pragma unroll
    for (int k2 = 0; k2 < 8; k2++) buf[line*cs + (k1 + 8*k2)*rs] = vv[q][k2];
  }
  __syncthreads();
}

// load spectrum, Hermitian-extend, inverse 2D FFT (unnormalized)
__device__ void load_herm_inv(float2* buf, const float2* stw, const float2* s, int tid){
  for (int e = tid; e < NMODE; e += 256){
    int xx = e/33, yy = e - xx*33;
    buf[xx*65 + yy] = s[e];
  }
  __syncthreads();
  for (int e = tid; e < 64*31; e += 256){
    int xx = e/31, yy = 33 + (e - (e/31)*31);
    float2 v = buf[((64-xx)&63)*65 + (64-yy)];
    buf[xx*65 + yy] = make_float2(v.x, -v.y);
  }
  __syncthreads();
  fft64_pass<1>(buf, stw, tid, 0);
  fft64_pass<1>(buf, stw, tid, 1);
}

// ---------------- FFT kernels ----------------
__global__ __launch_bounds__(256) void k_fft_fwd(){
  __shared__ float2 buf[64*65];
  __shared__ float2 stw[64];
  int tid = threadIdx.x, img = blockIdx.x;
  if (tid < 64) stw[tid] = g_tw[tid];
  const float* s = g_h + (size_t)img*NPIX;
  for (int e = tid; e < NPIX; e += 256) buf[(e>>6)*65 + (e&63)] = make_float2(s[e], 0.f);
  __syncthreads();
  fft64_pass<-1>(buf, stw, tid, 0);
  fft64_pass<-1>(buf, stw, tid, 1);
  float2* d = g_hf + (size_t)img*NMODE;
  for (int e = tid; e < NMODE; e += 256){
    int xx = e/33, yy = e - xx*33;
    d[e] = buf[xx*65 + yy];
  }
}

__global__ __launch_bounds__(256) void k_inv_z(){
  __shared__ float2 buf[64*65];
  __shared__ float2 stw[64];
  int tid = threadIdx.x, img = blockIdx.x;
  if (tid < 64) stw[tid] = g_tw[tid];
  load_herm_inv(buf, stw, g_zf + (size_t)img*NMODE, tid);
  float* d = g_z + (size_t)img*NPIX;
  for (int e = tid; e < NPIX; e += 256){
    float v = buf[(e>>6)*65 + (e&63)].x * (1.f/4096.f);
    d[e] = 1.f/(1.f + expf(-v));
  }
}

// irfft2(rf) -> r=sigmoid -> rh = r*h -> rfft2(rh) -> g_hf   (fused)
__global__ __launch_bounds__(256) void k_invr_fwd(){
  __shared__ float2 buf[64*65];
  __shared__ float2 stw[64];
  int tid = threadIdx.x, img = blockIdx.x;
  if (tid < 64) stw[tid] = g_tw[tid];
  load_herm_inv(buf, stw, g_rf + (size_t)img*NMODE, tid);
  const float* hp = g_h + (size_t)img*NPIX;
  for (int e = tid; e < NPIX; e += 256){
    int pos = (e>>6)*65 + (e&63);
    float v = buf[pos].x * (1.f/4096.f);
    float r = 1.f/(1.f + expf(-v));
    buf[pos] = make_float2(r*hp[e], 0.f);
  }
  __syncthreads();
  fft64_pass<-1>(buf, stw, tid, 0);
  fft64_pass<-1>(buf, stw, tid, 1);
  float2* d = g_hf + (size_t)img*NMODE;
  for (int e = tid; e < NMODE; e += 256){
    int xx = e/33, yy = e - xx*33;
    d[e] = buf[xx*65 + yy];
  }
}

// irfft2(nf) -> nh=tanh -> h = (1-z)*h + z*nh
__global__ __launch_bounds__(256) void k_inv_n(){
  __shared__ float2 buf[64*65];
  __shared__ float2 stw[64];
  int tid = threadIdx.x, img = blockIdx.x;
  if (tid < 64) stw[tid] = g_tw[tid];
  load_herm_inv(buf, stw, g_rf + (size_t)img*NMODE, tid);
  float* hp = g_h + (size_t)img*NPIX;
  const float* zp = g_z + (size_t)img*NPIX;
  for (int e = tid; e < NPIX; e += 256){
    float v = buf[(e>>6)*65 + (e&63)].x * (1.f/4096.f);
    float nh = tanhf(v);
    float z = zp[e], h = hp[e];
    hp[e] = h + z*(nh - h);
  }
}

// ---------------- spectral channel mix ----------------
// NG=2: hf -> (zf with Wt[0], rf with Wt[1]).  NG=1: hf -> rf with Wt[2].
// CTA = 8 modes; warp = 1 mode; lane o handles out-channels o and o+32, all 16 b.
template<int NG>
__global__ __launch_bounds__(256,2) void k_mix(){
  extern __shared__ float2 sh[];   // [ml][i][b] at ml*1088 + i*17 + b
  int tid = threadIdx.x;
  int m0 = blockIdx.x * 8;
  #pragma unroll
  for (int it = 0; it < 4; it++){
    int img = tid + it*256;
    const float4* p = (const float4*)(g_hf + (size_t)img*NMODE + m0);
    float2* q = sh + (img&63)*17 + (img>>6);
    #pragma unroll
    for (int c = 0; c < 4; c++){
      float4 v = p[c];
      q[(2*c)*1088]   = make_float2(v.x, v.y);
      q[(2*c+1)*1088] = make_float2(v.z, v.w);
    }
  }
  __syncthreads();
  int ml = tid >> 5, o = tid & 31;
  const float2* shm = sh + ml*1088;
  #pragma unroll
  for (int g = 0; g < NG; g++){
    const float2* Wm = g_Wt[NG==1 ? 2 : g] + (size_t)(m0+ml)*4096;
    float2* dst = (NG==2 && g==0) ? g_zf : g_rf;
    ull acc0[16], acc1[16];
    #pragma unroll
    for (int b = 0; b < 16; b++){ acc0[b]=0ull; acc1[b]=0ull; }
    #pragma unroll 2
    for (int i = 0; i < 64; i++){
      float2 w0 = Wm[i*64 + o];
      float2 w1 = Wm[i*64 + o + 32];
      ull a1 = pack2(w0.x, w0.x), a2 = pack2(-w0.y, w0.y);
      ull b1 = pack2(w1.x, w1.x), b2 = pack2(-w1.y, w1.y);
      const float2* hrow = shm + i*17;
      #pragma unroll
      for (int b = 0; b < 16; b++){
        float2 hv = hrow[b];
        ull h  = pack2(hv.x, hv.y);
        ull hs = pack2(hv.y, hv.x);
        acc0[b] = ffma2(h, a1, acc0[b]);
        acc0[b] = ffma2(hs, a2, acc0[b]);
        acc1[b] = ffma2(h, b1, acc1[b]);
        acc1[b] = ffma2(hs, b2, acc1[b]);
      }
    }
    ull* dq = (ull*)dst;
    #pragma unroll
    for (int b = 0; b < 16; b++){
      dq[(size_t)(b*64 + o)*NMODE + m0 + ml]      = acc0[b];
      dq[(size_t)(b*64 + o + 32)*NMODE + m0 + ml] = acc1[b];
    }
  }
}

// y[b][t][x][y] = sum_w h[b][w][x][y]*Wo[w] + bo
__global__ __launch_bounds__(256) void k_out(float* __restrict__ out,
    const float* __restrict__ Wo, const float* __restrict__ bo, int t){
  int idx = blockIdx.x*256 + threadIdx.x;   // 65536 = 16*4096
  int b = idx >> 12, xy = idx & 4095;
  float s = bo[0];
  const float* hp = g_h + (size_t)(b<<6)*NPIX + xy;
  #pragma unroll 8
  for (int w = 0; w < 64; w++) s += hp[(size_t)w*NPIX] * Wo[w];
  out[(size_t)((b*TSTEPS + t) << 12) + xy] = s;
}

// ---------------- launch ----------------
#define MIX_SMEM (8704*sizeof(float2))

extern "C" void kernel_launch(void* const* d_in, const int* in_sizes, int n_in,
                              void* d_out, int out_size){
  const float* x   = (const float*)d_in[0];
  const float* Wi  = (const float*)d_in[2];
  const float* bi  = (const float*)d_in[3];
  const float* Wo  = (const float*)d_in[4];
  const float* bo  = (const float*)d_in[5];
  const float* Wzr = (const float*)d_in[6];
  const float* Wzi = (const float*)d_in[7];
  const float* Wrr = (const float*)d_in[8];
  const float* Wri = (const float*)d_in[9];
  const float* Whr = (const float*)d_in[10];
  const float* Whi = (const float*)d_in[11];
  float* out = (float*)d_out;

  cudaFuncSetAttribute(k_mix<2>, cudaFuncAttributeMaxDynamicSharedMemorySize, (int)MIX_SMEM);
  cudaFuncSetAttribute(k_mix<1>, cudaFuncAttributeMaxDynamicSharedMemorySize, (int)MIX_SMEM);

  k_twid<<<1,64>>>();
  dim3 tb(32,8), tg(66,128);
  k_wtrans<<<tg,tb>>>(Wzr, Wzi, 0);
  k_wtrans<<<tg,tb>>>(Wrr, Wri, 1);
  k_wtrans<<<tg,tb>>>(Whr, Whi, 2);
  k_inmap<<<16384,256>>>(x, Wi, bi);

  for (int t = 0; t < TSTEPS; t++){
    k_fft_fwd<<<NIMG,256>>>();                     // h -> hf
    k_mix<2><<<NMODE/8,256,MIX_SMEM>>>();          // hf -> zf, rf
    k_inv_z<<<NIMG,256>>>();                       // zf -> z (sigmoid)
    k_invr_fwd<<<NIMG,256>>>();                    // rf -> r*h -> hf
    k_mix<1><<<NMODE/8,256,MIX_SMEM>>>();          // hf -> nf (in rf)
    k_inv_n<<<NIMG,256>>>();                       // nf -> tanh, GRU update of h
    k_out<<<256,256>>>(out, Wo, bo, t);            // y_t = h @ Wo + bo
  }
}